// round 10
// baseline (speedup 1.0000x reference)
#include <cuda_runtime.h>
#include <cstdint>

// ---------------------------------------------------------------------------
// Exact integer replication of the reference gate-level fp32 adder circuit.
// Words in IEEE layout: bit31=sign, [30:23]=exp, [22:0]=mant.
// Matches the circuit, NOT IEEE (truncated subnormals, subnormal mantissa path
// takes top 23 bits unshifted, big-diff at ediff>=24, exact cancel -> +0,
// overflow checked on computed_e pre-cancel).
// ---------------------------------------------------------------------------
__device__ __forceinline__ uint32_t fpadd_circuit(uint32_t ua, uint32_t ub) {
    uint32_t sa = ua >> 31, sb = ub >> 31;
    uint32_t ea = (ua >> 23) & 0xFFu, eb = (ub >> 23) & 0xFFu;
    uint32_t ma = ua & 0x7FFFFFu, mb = ub & 0x7FFFFFu;

    uint32_t ha = (ea != 0u) ? 1u : 0u;
    uint32_t hb = (eb != 0u) ? 1u : 0u;
    uint32_t eaf = ha ? ea : 1u;
    uint32_t ebf = hb ? eb : 1u;

    uint32_t Ma = (ha << 27) | (ma << 4);
    uint32_t Mb = (hb << 27) | (mb << 4);
    uint32_t maga = (ha << 23) | ma;
    uint32_t magb = (hb << 23) | mb;

    bool exp_eq = (eaf == ebf);
    bool a_ge_b = (eaf > ebf) || (exp_eq && (maga >= magb));
    bool abs_eq = exp_eq && (maga == magb);

    uint32_t ediff = a_ge_b ? (eaf - ebf) : (ebf - eaf);
    bool big = (ediff >= 24u);

    uint32_t e_max  = a_ge_b ? eaf : ebf;
    uint32_t Ml     = a_ge_b ? Ma  : Mb;
    uint32_t Ms0    = a_ge_b ? Mb  : Ma;

    uint32_t Ms;
    bool shift_sticky;
    if (big) {
        Ms = 0u;
        shift_sticky = (Ms0 != 0u);
    } else {
        Ms = Ms0 >> ediff;
        shift_sticky = (Ms0 & ((1u << ediff) - 1u)) != 0u;
    }

    bool dsign = (sa != sb);
    uint32_t s_large = a_ge_b ? sa : sb;

    uint32_t mant_res, carry;
    if (dsign) {
        mant_res = (Ml - Ms - (shift_sticky ? 1u : 0u)) & 0x0FFFFFFFu;
        carry = 0u;
    } else {
        uint32_t s = Ml + Ms;
        carry = s >> 28;
        mant_res = s & 0x0FFFFFFFu;
    }

    uint32_t lzc = mant_res ? (uint32_t)(__clz(mant_res) - 4) : 28u;
    bool underflow = (lzc >= e_max);
    uint32_t norm = (mant_res << lzc) & 0x0FFFFFFFu;

    uint32_t e_after = (e_max - lzc) & 0xFFu;
    uint32_t e_normal = underflow ? 0u : e_after;
    uint32_t final_e_pre = carry ? ((e_max + 1u) & 0xFFu) : e_normal;

    uint32_t m_pre, r_pre;
    bool st_pre;
    if (carry) {
        m_pre  = mant_res >> 5;
        r_pre  = (mant_res >> 4) & 1u;
        st_pre = (mant_res & 0xFu) != 0u;
    } else {
        m_pre  = (norm >> 4) & 0x7FFFFFu;
        r_pre  = (norm >> 3) & 1u;
        st_pre = (norm & 0x7u) != 0u;
    }
    st_pre = st_pre || shift_sticky;

    uint32_t m_sel = underflow ? (mant_res >> 5) : m_pre;
    bool do_round = (r_pre != 0u) && (st_pre || ((m_sel & 1u) != 0u)) && !underflow;

    uint32_t m24 = m_sel + (do_round ? 1u : 0u);
    uint32_t rc = (m24 >> 23) & 1u;
    uint32_t m_final = m24 & 0x7FFFFFu;
    uint32_t computed_e = (final_e_pre + rc) & 0xFFu;

    bool cancel = dsign && abs_eq;
    uint32_t out_s = cancel ? 0u : s_large;
    uint32_t out_e = cancel ? 0u : computed_e;
    uint32_t out_m = cancel ? 0u : m_final;

    bool ea1 = (ea == 0xFFu), eb1 = (eb == 0xFFu);
    bool manz = (ma != 0u),   mbnz = (mb != 0u);
    bool a_inf = ea1 && !manz, b_inf = eb1 && !mbnz;
    bool any_nan = (ea1 && manz) || (eb1 && mbnz);
    bool res_nan = any_nan || (dsign && a_inf && b_inf);
    bool ovf = (computed_e == 0xFFu);

    uint32_t out = (out_s << 31) | (out_e << 23) | out_m;
    if (a_inf || b_inf || ovf) out = (s_large << 31) | 0x7F800000u;
    if (res_nan)               out = 0x7FFFFFFFu;
    return out;
}

#define SROWW   36                  // smem WORDS per row (144B: conflict-free LDS.128)
#define TROWS   32                  // rows per warp-tile
#define HALF_W  (TROWS * SROWW)     // 1152 words: one array (A or B) per stage
#define STAGE_W (2 * HALF_W)        // 2304 words per stage {A,B}
#define WARP_W  (2 * STAGE_W)       // 2 stages per warp
#define WPB     4                   // warps per block
#define SMEM_BYTES (WPB * WARP_W * 4)   // 73728 B

__device__ __forceinline__ void cpasync16(uint32_t saddr, const void* gptr) {
    asm volatile("cp.async.cg.shared.global [%0], [%1], 16;" :: "r"(saddr), "l"(gptr));
}

// 4 floats (0.0/1.0 words) -> 4-bit nibble, element0 = MSB of the nibble
__device__ __forceinline__ uint32_t nib4(uint4 v) {
    uint32_t s0 = __byte_perm(v.x, v.y, 0x0073);        // b0=x.b3, b1=y.b3
    uint32_t s1 = __byte_perm(v.z, v.w, 0x0073);
    uint32_t pk = __byte_perm(s0, s1, 0x5410) & 0x01010101u;
    return (pk * 0x08040201u) >> 24;                    // x<<3|y<<2|z<<1|w
}

// Warp-scope copy of one 32-row tile into a stage. Each lane copies 8 A-chunks
// and 8 B-chunks; commits ONE group for the stage.
__device__ __forceinline__ void warp_issue_copy(uint32_t stage_addr,
                                                const uint4* A4, const uint4* B4,
                                                int tile, int lane) {
    const uint4* Af = A4 + (size_t)tile * TROWS * 8;
    const uint4* Bf = B4 + (size_t)tile * TROWS * 8;
    const uint32_t saA = stage_addr;
    const uint32_t saB = stage_addr + HALF_W * 4;
    #pragma unroll
    for (int j = 0; j < 8; ++j) {
        int c = j * 32 + lane;                       // chunk 0..255: row c>>3, pos c&7
        uint32_t off = (uint32_t)(c >> 3) * (SROWW * 4) + (uint32_t)(c & 7) * 16;
        cpasync16(saA + off, Af + c);
        cpasync16(saB + off, Bf + c);
    }
    asm volatile("cp.async.commit_group;");
}

// Warp-scope compute+store of one staged tile. Lane l owns row l.
__device__ __forceinline__ void warp_compute_store(const uint32_t* stage,
                                                   uint32_t* O, int tile, int lane) {
    const uint32_t* sA = stage;
    const uint32_t* sB = stage + HALF_W;
    const uint4* ra = (const uint4*)(sA + lane * SROWW);
    const uint4* rb = (const uint4*)(sB + lane * SROWW);
    uint32_t ua = 0u, ub = 0u;
    #pragma unroll
    for (int k = 0; k < 8; ++k) {
        ua |= nib4(ra[k]) << (28 - 4 * k);
        ub |= nib4(rb[k]) << (28 - 4 * k);
    }
    uint32_t res = fpadd_circuit(ua, ub);

    const int row0 = tile * TROWS;
    const int sub  = lane >> 3;
    const uint32_t e0 = (lane & 7) << 2;
    #pragma unroll
    for (int k = 0; k < 8; ++k) {
        int idx  = (k << 2) + sub;                   // row idx held by lane idx
        uint32_t w = __shfl_sync(0xFFFFFFFFu, res, idx);
        uint4 o;
        o.x = (uint32_t)(((int32_t)(w << (e0 + 0))) >> 31) & 0x3F800000u;
        o.y = (uint32_t)(((int32_t)(w << (e0 + 1))) >> 31) & 0x3F800000u;
        o.z = (uint32_t)(((int32_t)(w << (e0 + 2))) >> 31) & 0x3F800000u;
        o.w = (uint32_t)(((int32_t)(w << (e0 + 3))) >> 31) & 0x3F800000u;
        *(uint4*)(O + (size_t)(row0 + idx) * 32 + e0) = o;
    }
}

__global__ void __launch_bounds__(128)
spike_fp32_adder_kernel(const uint4* __restrict__ A4,
                        const uint4* __restrict__ B4,
                        uint32_t* __restrict__ O,
                        int nrows, int ntiles, int twarps) {
    extern __shared__ __align__(16) uint32_t smem[];
    const int tid  = threadIdx.x;
    const int lane = tid & 31;
    const int wid  = tid >> 5;
    const int gw   = blockIdx.x * WPB + wid;         // global warp id

    // ---- tail rows (nrows % 32; dead for this shape), block 0 scalar ----
    if (blockIdx.x == 0) {
        int r = ntiles * TROWS + tid;
        if (r < nrows) {
            const uint4* Ar = A4 + (size_t)r * 8;
            const uint4* Br = B4 + (size_t)r * 8;
            uint32_t ua = 0u, ub = 0u;
            #pragma unroll
            for (int k = 0; k < 8; ++k) {
                ua |= nib4(Ar[k]) << (28 - 4 * k);
                ub |= nib4(Br[k]) << (28 - 4 * k);
            }
            uint32_t w = fpadd_circuit(ua, ub);
            #pragma unroll
            for (int k = 0; k < 8; ++k) {
                uint4 o;
                uint32_t e0 = k << 2;
                o.x = (uint32_t)(((int32_t)(w << (e0 + 0))) >> 31) & 0x3F800000u;
                o.y = (uint32_t)(((int32_t)(w << (e0 + 1))) >> 31) & 0x3F800000u;
                o.z = (uint32_t)(((int32_t)(w << (e0 + 2))) >> 31) & 0x3F800000u;
                o.w = (uint32_t)(((int32_t)(w << (e0 + 3))) >> 31) & 0x3F800000u;
                *(uint4*)(O + (size_t)r * 32 + e0) = o;
            }
        }
    }

    // ---- warp-autonomous 2-stage pipeline over this warp's tile stream ----
    uint32_t* wsm = smem + (size_t)wid * WARP_W;
    const uint32_t wsm_a = (uint32_t)__cvta_generic_to_shared(wsm);

    int tile = gw;
    if (tile >= ntiles) return;

    warp_issue_copy(wsm_a, A4, B4, tile, lane);      // prologue: stage 0

    int i = 0;
    for (; tile < ntiles; tile += twarps, ++i) {
        int next = tile + twarps;
        if (next < ntiles) {
            warp_issue_copy(wsm_a + ((i + 1) & 1) * STAGE_W * 4, A4, B4, next, lane);
            asm volatile("cp.async.wait_group 1;");
        } else {
            asm volatile("cp.async.wait_group 0;");
        }
        __syncwarp();                                // copies visible warp-wide
        warp_compute_store(wsm + (i & 1) * STAGE_W, O, tile, lane);
        __syncwarp();                                // reads done before stage reuse
    }
}

extern "C" void kernel_launch(void* const* d_in, const int* in_sizes, int n_in,
                              void* d_out, int out_size) {
    const uint4* A = (const uint4*)d_in[0];
    const uint4* B = (const uint4*)d_in[1];
    uint32_t* O = (uint32_t*)d_out;

    int nrows  = in_sizes[0] / 32;            // 524288
    int ntiles = nrows / TROWS;               // 16384 warp-tiles
    int blocks = 444;                         // 3 blocks x 148 SMs: one exact wave
    int twarps = blocks * WPB;                // 1776 warp streams

    cudaFuncSetAttribute(spike_fp32_adder_kernel,
                         cudaFuncAttributeMaxDynamicSharedMemorySize, SMEM_BYTES);
    spike_fp32_adder_kernel<<<blocks, 128, SMEM_BYTES>>>(A, B, O, nrows, ntiles, twarps);
}

// round 11
// speedup vs baseline: 1.0992x; 1.0992x over previous
#include <cuda_runtime.h>
#include <cstdint>

// ---------------------------------------------------------------------------
// Exact integer replication of the reference gate-level fp32 adder circuit.
// Words in IEEE layout: bit31=sign, [30:23]=exp, [22:0]=mant.
// Matches the circuit, NOT IEEE (truncated subnormals, subnormal mantissa path
// takes top 23 bits unshifted, big-diff at ediff>=24, exact cancel -> +0,
// overflow checked on computed_e pre-cancel).
// ---------------------------------------------------------------------------
__device__ __forceinline__ uint32_t fpadd_circuit(uint32_t ua, uint32_t ub) {
    uint32_t sa = ua >> 31, sb = ub >> 31;
    uint32_t ea = (ua >> 23) & 0xFFu, eb = (ub >> 23) & 0xFFu;
    uint32_t ma = ua & 0x7FFFFFu, mb = ub & 0x7FFFFFu;

    uint32_t ha = (ea != 0u) ? 1u : 0u;
    uint32_t hb = (eb != 0u) ? 1u : 0u;
    uint32_t eaf = ha ? ea : 1u;
    uint32_t ebf = hb ? eb : 1u;

    uint32_t Ma = (ha << 27) | (ma << 4);
    uint32_t Mb = (hb << 27) | (mb << 4);
    uint32_t maga = (ha << 23) | ma;
    uint32_t magb = (hb << 23) | mb;

    bool exp_eq = (eaf == ebf);
    bool a_ge_b = (eaf > ebf) || (exp_eq && (maga >= magb));
    bool abs_eq = exp_eq && (maga == magb);

    uint32_t ediff = a_ge_b ? (eaf - ebf) : (ebf - eaf);
    bool big = (ediff >= 24u);

    uint32_t e_max  = a_ge_b ? eaf : ebf;
    uint32_t Ml     = a_ge_b ? Ma  : Mb;
    uint32_t Ms0    = a_ge_b ? Mb  : Ma;

    uint32_t Ms;
    bool shift_sticky;
    if (big) {
        Ms = 0u;
        shift_sticky = (Ms0 != 0u);
    } else {
        Ms = Ms0 >> ediff;
        shift_sticky = (Ms0 & ((1u << ediff) - 1u)) != 0u;
    }

    bool dsign = (sa != sb);
    uint32_t s_large = a_ge_b ? sa : sb;

    uint32_t mant_res, carry;
    if (dsign) {
        mant_res = (Ml - Ms - (shift_sticky ? 1u : 0u)) & 0x0FFFFFFFu;
        carry = 0u;
    } else {
        uint32_t s = Ml + Ms;
        carry = s >> 28;
        mant_res = s & 0x0FFFFFFFu;
    }

    uint32_t lzc = mant_res ? (uint32_t)(__clz(mant_res) - 4) : 28u;
    bool underflow = (lzc >= e_max);
    uint32_t norm = (mant_res << lzc) & 0x0FFFFFFFu;

    uint32_t e_after = (e_max - lzc) & 0xFFu;
    uint32_t e_normal = underflow ? 0u : e_after;
    uint32_t final_e_pre = carry ? ((e_max + 1u) & 0xFFu) : e_normal;

    uint32_t m_pre, r_pre;
    bool st_pre;
    if (carry) {
        m_pre  = mant_res >> 5;
        r_pre  = (mant_res >> 4) & 1u;
        st_pre = (mant_res & 0xFu) != 0u;
    } else {
        m_pre  = (norm >> 4) & 0x7FFFFFu;
        r_pre  = (norm >> 3) & 1u;
        st_pre = (norm & 0x7u) != 0u;
    }
    st_pre = st_pre || shift_sticky;

    uint32_t m_sel = underflow ? (mant_res >> 5) : m_pre;
    bool do_round = (r_pre != 0u) && (st_pre || ((m_sel & 1u) != 0u)) && !underflow;

    uint32_t m24 = m_sel + (do_round ? 1u : 0u);
    uint32_t rc = (m24 >> 23) & 1u;
    uint32_t m_final = m24 & 0x7FFFFFu;
    uint32_t computed_e = (final_e_pre + rc) & 0xFFu;

    bool cancel = dsign && abs_eq;
    uint32_t out_s = cancel ? 0u : s_large;
    uint32_t out_e = cancel ? 0u : computed_e;
    uint32_t out_m = cancel ? 0u : m_final;

    bool ea1 = (ea == 0xFFu), eb1 = (eb == 0xFFu);
    bool manz = (ma != 0u),   mbnz = (mb != 0u);
    bool a_inf = ea1 && !manz, b_inf = eb1 && !mbnz;
    bool any_nan = (ea1 && manz) || (eb1 && mbnz);
    bool res_nan = any_nan || (dsign && a_inf && b_inf);
    bool ovf = (computed_e == 0xFFu);

    uint32_t out = (out_s << 31) | (out_e << 23) | out_m;
    if (a_inf || b_inf || ovf) out = (s_large << 31) | 0x7F800000u;
    if (res_nan)               out = 0x7FFFFFFFu;
    return out;
}

#define RPB        128                 // rows per block (== threads)
#define TILE_BYTES (RPB * 128)         // 16384 B per input array

// 4 floats (0.0/1.0 words) -> 4-bit nibble, element0 = MSB of the nibble
__device__ __forceinline__ uint32_t nib4(uint4 v) {
    uint32_t s0 = __byte_perm(v.x, v.y, 0x0073);        // b0=x.b3, b1=y.b3
    uint32_t s1 = __byte_perm(v.z, v.w, 0x0073);
    uint32_t pk = __byte_perm(s0, s1, 0x5410) & 0x01010101u;
    return (pk * 0x08040201u) >> 24;                    // x<<3|y<<2|z<<1|w
}

__device__ __forceinline__ void bulk_copy(uint32_t dst_smem, const void* src,
                                          uint32_t bytes, uint32_t bar) {
    asm volatile(
        "cp.async.bulk.shared::cta.global.mbarrier::complete_tx::bytes "
        "[%0], [%1], %2, [%3];"
        :: "r"(dst_smem), "l"(src), "r"(bytes), "r"(bar) : "memory");
}

__global__ void __launch_bounds__(128)
spike_fp32_adder_kernel(const uint4* __restrict__ A4,
                        const uint4* __restrict__ B4,
                        uint32_t* __restrict__ O,
                        int nrows) {
    __shared__ __align__(16) uint32_t sA[RPB * 32];   // 16 KB, natural layout
    __shared__ __align__(16) uint32_t sB[RPB * 32];   // 16 KB
    __shared__ uint64_t bar;

    const int tid = threadIdx.x;
    const int row0 = blockIdx.x * RPB;
    if (row0 >= nrows) return;

    if (row0 + RPB <= nrows) {
        // ---- Phase 1: two single-instruction 16KB bulk copies (TMA path) ----
        const uint32_t barA = (uint32_t)__cvta_generic_to_shared(&bar);
        if (tid == 0) {
            asm volatile("mbarrier.init.shared.b64 [%0], %1;"
                         :: "r"(barA), "r"(1) : "memory");
            asm volatile("fence.proxy.async.shared::cta;" ::: "memory");
        }
        __syncthreads();
        if (tid == 0) {
            asm volatile("mbarrier.arrive.expect_tx.shared.b64 _, [%0], %1;"
                         :: "r"(barA), "r"(2u * TILE_BYTES) : "memory");
            bulk_copy((uint32_t)__cvta_generic_to_shared(sA),
                      A4 + (size_t)row0 * 8, TILE_BYTES, barA);
            bulk_copy((uint32_t)__cvta_generic_to_shared(sB),
                      B4 + (size_t)row0 * 8, TILE_BYTES, barA);
        }
        // wait (parity 0) with acquire so generic LDS after sees the data
        {
            uint32_t done = 0;
            while (!done) {
                asm volatile(
                    "{\n\t.reg .pred p;\n\t"
                    "mbarrier.try_wait.parity.acquire.cta.shared::cta.b64 p, [%1], %2;\n\t"
                    "selp.b32 %0, 1, 0, p;\n\t}"
                    : "=r"(done) : "r"(barA), "r"(0u) : "memory");
            }
        }

        // ---- Phase 2: own row, XOR chunk order -> conflict-free LDS.128 ----
        const int l7 = tid & 7;
        const uint4* ra = (const uint4*)sA + tid * 8;
        const uint4* rb = (const uint4*)sB + tid * 8;
        uint32_t ua = 0u, ub = 0u;
        #pragma unroll
        for (int m = 0; m < 8; ++m) {
            int j = m ^ l7;                       // distinct bank-group per lane phase
            int sh = 28 - 4 * j;
            ua |= nib4(ra[j]) << sh;
            ub |= nib4(rb[j]) << sh;
        }
        uint32_t res = fpadd_circuit(ua, ub);

        // ---- Phase 3: shfl scatter, coalesced 16B stores ----
        const int lane  = tid & 31;
        const int wrow0 = row0 + (tid & ~31);
        const int sub   = lane >> 3;
        const uint32_t e0 = (lane & 7) << 2;
        #pragma unroll
        for (int k = 0; k < 8; ++k) {
            int idx  = (k << 2) + sub;
            uint32_t w = __shfl_sync(0xFFFFFFFFu, res, idx);
            uint4 o;
            o.x = (uint32_t)(((int32_t)(w << (e0 + 0))) >> 31) & 0x3F800000u;
            o.y = (uint32_t)(((int32_t)(w << (e0 + 1))) >> 31) & 0x3F800000u;
            o.z = (uint32_t)(((int32_t)(w << (e0 + 2))) >> 31) & 0x3F800000u;
            o.w = (uint32_t)(((int32_t)(w << (e0 + 3))) >> 31) & 0x3F800000u;
            *(uint4*)(O + (size_t)(wrow0 + idx) * 32 + e0) = o;
        }
    } else {
        // ---- tail path (dead for nrows % 128 == 0): scalar per-thread ----
        int r = row0 + tid;
        if (r < nrows) {
            const uint4* Ar = A4 + (size_t)r * 8;
            const uint4* Br = B4 + (size_t)r * 8;
            uint32_t ua = 0u, ub = 0u;
            #pragma unroll
            for (int k = 0; k < 8; ++k) {
                ua |= nib4(Ar[k]) << (28 - 4 * k);
                ub |= nib4(Br[k]) << (28 - 4 * k);
            }
            uint32_t w = fpadd_circuit(ua, ub);
            #pragma unroll
            for (int k = 0; k < 8; ++k) {
                uint4 o;
                uint32_t e0 = k << 2;
                o.x = (uint32_t)(((int32_t)(w << (e0 + 0))) >> 31) & 0x3F800000u;
                o.y = (uint32_t)(((int32_t)(w << (e0 + 1))) >> 31) & 0x3F800000u;
                o.z = (uint32_t)(((int32_t)(w << (e0 + 2))) >> 31) & 0x3F800000u;
                o.w = (uint32_t)(((int32_t)(w << (e0 + 3))) >> 31) & 0x3F800000u;
                *(uint4*)(O + (size_t)r * 32 + e0) = o;
            }
        }
    }
}

extern "C" void kernel_launch(void* const* d_in, const int* in_sizes, int n_in,
                              void* d_out, int out_size) {
    const uint4* A = (const uint4*)d_in[0];
    const uint4* B = (const uint4*)d_in[1];
    uint32_t* O = (uint32_t*)d_out;

    int nrows  = in_sizes[0] / 32;                // 524288
    int blocks = (nrows + RPB - 1) / RPB;         // 4096

    spike_fp32_adder_kernel<<<blocks, RPB>>>(A, B, O, nrows);
}

// round 12
// speedup vs baseline: 1.1576x; 1.0532x over previous
#include <cuda_runtime.h>
#include <cstdint>

// ---------------------------------------------------------------------------
// Exact integer replication of the reference gate-level fp32 adder circuit.
// Words in IEEE layout: bit31=sign, [30:23]=exp, [22:0]=mant.
// Matches the circuit, NOT IEEE (truncated subnormals, subnormal mantissa path
// takes top 23 bits unshifted, big-diff at ediff>=24, exact cancel -> +0,
// overflow checked on computed_e pre-cancel).
// ---------------------------------------------------------------------------
__device__ __forceinline__ uint32_t fpadd_circuit(uint32_t ua, uint32_t ub) {
    uint32_t sa = ua >> 31, sb = ub >> 31;
    uint32_t ea = (ua >> 23) & 0xFFu, eb = (ub >> 23) & 0xFFu;
    uint32_t ma = ua & 0x7FFFFFu, mb = ub & 0x7FFFFFu;

    uint32_t ha = (ea != 0u) ? 1u : 0u;
    uint32_t hb = (eb != 0u) ? 1u : 0u;
    uint32_t eaf = ha ? ea : 1u;
    uint32_t ebf = hb ? eb : 1u;

    uint32_t Ma = (ha << 27) | (ma << 4);
    uint32_t Mb = (hb << 27) | (mb << 4);
    uint32_t maga = (ha << 23) | ma;
    uint32_t magb = (hb << 23) | mb;

    bool exp_eq = (eaf == ebf);
    bool a_ge_b = (eaf > ebf) || (exp_eq && (maga >= magb));
    bool abs_eq = exp_eq && (maga == magb);

    uint32_t ediff = a_ge_b ? (eaf - ebf) : (ebf - eaf);
    bool big = (ediff >= 24u);

    uint32_t e_max  = a_ge_b ? eaf : ebf;
    uint32_t Ml     = a_ge_b ? Ma  : Mb;
    uint32_t Ms0    = a_ge_b ? Mb  : Ma;

    uint32_t Ms;
    bool shift_sticky;
    if (big) {
        Ms = 0u;
        shift_sticky = (Ms0 != 0u);
    } else {
        Ms = Ms0 >> ediff;
        shift_sticky = (Ms0 & ((1u << ediff) - 1u)) != 0u;
    }

    bool dsign = (sa != sb);
    uint32_t s_large = a_ge_b ? sa : sb;

    uint32_t mant_res, carry;
    if (dsign) {
        mant_res = (Ml - Ms - (shift_sticky ? 1u : 0u)) & 0x0FFFFFFFu;
        carry = 0u;
    } else {
        uint32_t s = Ml + Ms;
        carry = s >> 28;
        mant_res = s & 0x0FFFFFFFu;
    }

    uint32_t lzc = mant_res ? (uint32_t)(__clz(mant_res) - 4) : 28u;
    bool underflow = (lzc >= e_max);
    uint32_t norm = (mant_res << lzc) & 0x0FFFFFFFu;

    uint32_t e_after = (e_max - lzc) & 0xFFu;
    uint32_t e_normal = underflow ? 0u : e_after;
    uint32_t final_e_pre = carry ? ((e_max + 1u) & 0xFFu) : e_normal;

    uint32_t m_pre, r_pre;
    bool st_pre;
    if (carry) {
        m_pre  = mant_res >> 5;
        r_pre  = (mant_res >> 4) & 1u;
        st_pre = (mant_res & 0xFu) != 0u;
    } else {
        m_pre  = (norm >> 4) & 0x7FFFFFu;
        r_pre  = (norm >> 3) & 1u;
        st_pre = (norm & 0x7u) != 0u;
    }
    st_pre = st_pre || shift_sticky;

    uint32_t m_sel = underflow ? (mant_res >> 5) : m_pre;
    bool do_round = (r_pre != 0u) && (st_pre || ((m_sel & 1u) != 0u)) && !underflow;

    uint32_t m24 = m_sel + (do_round ? 1u : 0u);
    uint32_t rc = (m24 >> 23) & 1u;
    uint32_t m_final = m24 & 0x7FFFFFu;
    uint32_t computed_e = (final_e_pre + rc) & 0xFFu;

    bool cancel = dsign && abs_eq;
    uint32_t out_s = cancel ? 0u : s_large;
    uint32_t out_e = cancel ? 0u : computed_e;
    uint32_t out_m = cancel ? 0u : m_final;

    bool ea1 = (ea == 0xFFu), eb1 = (eb == 0xFFu);
    bool manz = (ma != 0u),   mbnz = (mb != 0u);
    bool a_inf = ea1 && !manz, b_inf = eb1 && !mbnz;
    bool any_nan = (ea1 && manz) || (eb1 && mbnz);
    bool res_nan = any_nan || (dsign && a_inf && b_inf);
    bool ovf = (computed_e == 0xFFu);

    uint32_t out = (out_s << 31) | (out_e << 23) | out_m;
    if (a_inf || b_inf || ovf) out = (s_large << 31) | 0x7F800000u;
    if (res_nan)               out = 0x7FFFFFFFu;
    return out;
}

#define RPB         128                 // rows per block (== threads)
#define WARP_ROWS   32                  // rows per warp slice
#define SLICE_BYTES (WARP_ROWS * 128)   // 4096 B per input per warp

// 4 floats (0.0/1.0 words) -> 4-bit nibble, element0 = MSB of the nibble
__device__ __forceinline__ uint32_t nib4(uint4 v) {
    uint32_t s0 = __byte_perm(v.x, v.y, 0x0073);        // b0=x.b3, b1=y.b3
    uint32_t s1 = __byte_perm(v.z, v.w, 0x0073);
    uint32_t pk = __byte_perm(s0, s1, 0x5410) & 0x01010101u;
    return (pk * 0x08040201u) >> 24;                    // x<<3|y<<2|z<<1|w
}

__device__ __forceinline__ void bulk_copy(uint32_t dst_smem, const void* src,
                                          uint32_t bytes, uint32_t bar) {
    asm volatile(
        "cp.async.bulk.shared::cta.global.mbarrier::complete_tx::bytes "
        "[%0], [%1], %2, [%3];"
        :: "r"(dst_smem), "l"(src), "r"(bytes), "r"(bar) : "memory");
}

__global__ void __launch_bounds__(128)
spike_fp32_adder_kernel(const uint4* __restrict__ A4,
                        const uint4* __restrict__ B4,
                        uint32_t* __restrict__ O,
                        int nrows) {
    __shared__ __align__(16) uint32_t sA[RPB * 32];   // 16 KB
    __shared__ __align__(16) uint32_t sB[RPB * 32];   // 16 KB
    __shared__ __align__(8)  uint64_t bars[4];        // one mbarrier per warp

    const int tid  = threadIdx.x;
    const int lane = tid & 31;
    const int wid  = tid >> 5;
    const int row0 = blockIdx.x * RPB;
    if (row0 >= nrows) return;

    if (row0 + RPB <= nrows) {
        // ---- Phase 1: warp-private TMA slices, zero block-level sync ----
        const int wrow0 = row0 + wid * WARP_ROWS;         // warp's first row
        uint32_t* wA = sA + wid * WARP_ROWS * 32;
        uint32_t* wB = sB + wid * WARP_ROWS * 32;
        const uint32_t barA = (uint32_t)__cvta_generic_to_shared(&bars[wid]);

        if (lane == 0) {
            asm volatile("mbarrier.init.shared.b64 [%0], %1;"
                         :: "r"(barA), "r"(1) : "memory");
            asm volatile("fence.proxy.async.shared::cta;" ::: "memory");
        }
        __syncwarp();
        if (lane == 0) {
            asm volatile("mbarrier.arrive.expect_tx.shared.b64 _, [%0], %1;"
                         :: "r"(barA), "r"(2u * SLICE_BYTES) : "memory");
            bulk_copy((uint32_t)__cvta_generic_to_shared(wA),
                      A4 + (size_t)wrow0 * 8, SLICE_BYTES, barA);
            bulk_copy((uint32_t)__cvta_generic_to_shared(wB),
                      B4 + (size_t)wrow0 * 8, SLICE_BYTES, barA);
        }
        // all lanes wait on THIS warp's barrier only (acquire for generic LDS)
        {
            uint32_t done = 0;
            while (!done) {
                asm volatile(
                    "{\n\t.reg .pred p;\n\t"
                    "mbarrier.try_wait.parity.acquire.cta.shared::cta.b64 p, [%1], %2;\n\t"
                    "selp.b32 %0, 1, 0, p;\n\t}"
                    : "=r"(done) : "r"(barA), "r"(0u) : "memory");
            }
        }

        // ---- Phase 2: own row, XOR chunk order -> conflict-free LDS.128 ----
        const int l7 = lane & 7;
        const uint4* ra = (const uint4*)wA + lane * 8;
        const uint4* rb = (const uint4*)wB + lane * 8;
        uint32_t ua = 0u, ub = 0u;
        #pragma unroll
        for (int m = 0; m < 8; ++m) {
            int j = m ^ l7;                       // distinct bank-group per lane phase
            int sh = 28 - 4 * j;
            ua |= nib4(ra[j]) << sh;
            ub |= nib4(rb[j]) << sh;
        }
        uint32_t res = fpadd_circuit(ua, ub);

        // ---- Phase 3: shfl scatter, coalesced 16B stores (warp-local) ----
        const int sub = lane >> 3;
        const uint32_t e0 = (lane & 7) << 2;
        #pragma unroll
        for (int k = 0; k < 8; ++k) {
            int idx  = (k << 2) + sub;            // row idx held by lane idx
            uint32_t w = __shfl_sync(0xFFFFFFFFu, res, idx);
            uint4 o;
            o.x = (uint32_t)(((int32_t)(w << (e0 + 0))) >> 31) & 0x3F800000u;
            o.y = (uint32_t)(((int32_t)(w << (e0 + 1))) >> 31) & 0x3F800000u;
            o.z = (uint32_t)(((int32_t)(w << (e0 + 2))) >> 31) & 0x3F800000u;
            o.w = (uint32_t)(((int32_t)(w << (e0 + 3))) >> 31) & 0x3F800000u;
            *(uint4*)(O + (size_t)(wrow0 + idx) * 32 + e0) = o;
        }
    } else {
        // ---- tail path (dead for nrows % 128 == 0): scalar per-thread ----
        int r = row0 + tid;
        if (r < nrows) {
            const uint4* Ar = A4 + (size_t)r * 8;
            const uint4* Br = B4 + (size_t)r * 8;
            uint32_t ua = 0u, ub = 0u;
            #pragma unroll
            for (int k = 0; k < 8; ++k) {
                ua |= nib4(Ar[k]) << (28 - 4 * k);
                ub |= nib4(Br[k]) << (28 - 4 * k);
            }
            uint32_t w = fpadd_circuit(ua, ub);
            #pragma unroll
            for (int k = 0; k < 8; ++k) {
                uint4 o;
                uint32_t e0 = k << 2;
                o.x = (uint32_t)(((int32_t)(w << (e0 + 0))) >> 31) & 0x3F800000u;
                o.y = (uint32_t)(((int32_t)(w << (e0 + 1))) >> 31) & 0x3F800000u;
                o.z = (uint32_t)(((int32_t)(w << (e0 + 2))) >> 31) & 0x3F800000u;
                o.w = (uint32_t)(((int32_t)(w << (e0 + 3))) >> 31) & 0x3F800000u;
                *(uint4*)(O + (size_t)r * 32 + e0) = o;
            }
        }
    }
}

extern "C" void kernel_launch(void* const* d_in, const int* in_sizes, int n_in,
                              void* d_out, int out_size) {
    const uint4* A = (const uint4*)d_in[0];
    const uint4* B = (const uint4*)d_in[1];
    uint32_t* O = (uint32_t*)d_out;

    int nrows  = in_sizes[0] / 32;                // 524288
    int blocks = (nrows + RPB - 1) / RPB;         // 4096

    spike_fp32_adder_kernel<<<blocks, RPB>>>(A, B, O, nrows);
}